// round 14
// baseline (speedup 1.0000x reference)
#include <cuda_runtime.h>
#include <cuda_fp16.h>
#include <cstdint>

#define TOK    4096   // B*S
#define DMODEL 1024
#define NH     16
#define HDIM   64
#define NE     8
#define FF     4096
#define SEQ    1024

// ---------------- scratch (device globals) ----------------
__device__ float  g_h  [TOK*DMODEL];
__device__ float  g_hn [TOK*DMODEL];
__device__ float  g_y2 [(size_t)2*TOK*DMODEL];
__device__ int    g_ecnt[NE];
__device__ int    g_elist[NE*TOK];
__device__ float  g_gate[2*TOK];

// fp16 buffers
__device__ __half g_qn16 [TOK*DMODEL];
__device__ __half g_ctx16[TOK*DMODEL];
__device__ __half g_hn16 [TOK*DMODEL];
__device__ __half g_hg16 [(size_t)2*TOK*FF];
__device__ __half g_q16  [TOK*DMODEL];
__device__ __half g_k16  [TOK*DMODEL];
__device__ __half g_v16  [TOK*DMODEL];
__device__ __half g_wq16 [DMODEL*DMODEL];
__device__ __half g_wk16 [DMODEL*DMODEL];
__device__ __half g_wv16 [DMODEL*DMODEL];
__device__ __half g_wo16 [DMODEL*DMODEL];
__device__ __half g_w1h  [(size_t)NE*FF*DMODEL];
__device__ __half g_w3h  [(size_t)NE*FF*DMODEL];
__device__ __half g_w2h  [(size_t)NE*DMODEL*FF];

// fp32 buf ids
#define BUF_H   0
#define BUF_HN  1
#define BUF_Y2  2
#define BUF_EXT (-1)

__device__ __forceinline__ float* resolve_buf(int id, const float* ext) {
    switch (id) {
        case BUF_H:   return g_h;
        case BUF_HN:  return g_hn;
        case BUF_Y2:  return g_y2;
    }
    return (float*)ext;
}

// half buf ids
#define HB_QN16  0
#define HB_CTX16 1
#define HB_HN16  2
#define HB_HG16  3
#define HB_WO    7
#define HB_W2    10

__device__ __forceinline__ __half* resolve_hbuf(int id) {
    switch (id) {
        case HB_QN16:  return g_qn16;
        case HB_CTX16: return g_ctx16;
        case HB_HN16:  return g_hn16;
        case HB_HG16:  return g_hg16;
        case HB_WO:    return g_wo16;
        case HB_W2:    return g_w2h;
    }
    return g_qn16;
}

// ---------------- helpers ----------------
__device__ __forceinline__ void mma_f16(float* c, const uint32_t* a, const uint32_t* b) {
    asm volatile(
        "mma.sync.aligned.m16n8k16.row.col.f32.f16.f16.f32 "
        "{%0,%1,%2,%3}, {%4,%5,%6,%7}, {%8,%9}, {%0,%1,%2,%3};"
        : "+f"(c[0]), "+f"(c[1]), "+f"(c[2]), "+f"(c[3])
        : "r"(a[0]), "r"(a[1]), "r"(a[2]), "r"(a[3]), "r"(b[0]), "r"(b[1]));
}

__device__ __forceinline__ uint32_t packh2(float x, float y) {
    __half2 h = __floats2half2_rn(x, y);
    return *(uint32_t*)&h;
}

#define CP16(dst, src) asm volatile("cp.async.cg.shared.global [%0], [%1], 16;\n" :: "r"(dst), "l"(src))
#define CPCOMMIT()     asm volatile("cp.async.commit_group;\n" ::: "memory")
#define CPWAIT(n)      asm volatile("cp.async.wait_group %0;\n" :: "n"(n) : "memory")

// smem tile: rows x 64 halves (128B rows), 16B-chunk XOR swizzle with row&7
#define LDH(base, row, chunk, off) \
    (*(const uint32_t*)&(base)[(row)*64 + ((((chunk) ^ ((row) & 7)) & 7) << 3) + (off)])

// ldmatrix A 16x16 fragment (a0..a3) from swizzled tile. base = u32 smem addr of stage.
__device__ __forceinline__ void ldsm_a(uint32_t* a, uint32_t base, int row0, int ks, int lane) {
    int q = lane & 7, seg = lane >> 3;
    int row = row0 + ((seg & 1) << 3) + q;
    int ch  = 2*ks + (seg >> 1);
    uint32_t addr = base + (uint32_t)((row*64 + ((ch ^ (row & 7)) << 3)) << 1);
    asm volatile("ldmatrix.sync.aligned.m8n8.x4.shared.b16 {%0,%1,%2,%3}, [%4];"
        : "=r"(a[0]), "=r"(a[1]), "=r"(a[2]), "=r"(a[3]) : "r"(addr));
}

// ldmatrix two B 8x16 fragments: b0 = rows row0..row0+7, b1 = rows row0+8..+15
__device__ __forceinline__ void ldsm_b2(uint32_t* b0, uint32_t* b1, uint32_t base, int row0, int ks, int lane) {
    int q = lane & 7, seg = lane >> 3;
    int row = row0 + ((seg >> 1) << 3) + q;
    int ch  = 2*ks + (seg & 1);
    uint32_t addr = base + (uint32_t)((row*64 + ((ch ^ (row & 7)) << 3)) << 1);
    asm volatile("ldmatrix.sync.aligned.m8n8.x4.shared.b16 {%0,%1,%2,%3}, [%4];"
        : "=r"(b0[0]), "=r"(b0[1]), "=r"(b1[0]), "=r"(b1[1]) : "r"(addr));
}

// ---------------- fused f32 -> f16 conversion of all weights ----------------
__global__ void f2h_all(const float4* __restrict__ wq, const float4* __restrict__ wk,
                        const float4* __restrict__ wv, const float4* __restrict__ wo,
                        const float4* __restrict__ w1, const float4* __restrict__ w3,
                        const float4* __restrict__ w2)
{
    const size_t NW  = (size_t)DMODEL*DMODEL/4;   // 2^18
    const size_t NWE = (size_t)NE*FF*DMODEL/4;    // 2^23
    size_t i = (size_t)blockIdx.x*256 + threadIdx.x;
    if (i >= 4*NW + 3*NWE) return;
    const float4* src; __half2* dst; size_t off;
    if (i < 4*NW) {
        int seg = (int)(i >> 18); off = i & (NW - 1);
        src = (seg == 0) ? wq : (seg == 1) ? wk : (seg == 2) ? wv : wo;
        dst = (__half2*)((seg == 0) ? g_wq16 : (seg == 1) ? g_wk16 : (seg == 2) ? g_wv16 : g_wo16);
    } else {
        size_t j = i - 4*NW; int seg = (int)(j >> 23); off = j & (NWE - 1);
        src = (seg == 0) ? w1 : (seg == 1) ? w3 : w2;
        dst = (__half2*)((seg == 0) ? g_w1h : (seg == 1) ? g_w3h : g_w2h);
    }
    float4 v = src[off];
    dst[off*2    ] = __floats2half2_rn(v.x, v.y);
    dst[off*2 + 1] = __floats2half2_rn(v.z, v.w);
}

// ---------------- rmsnorm: optional fp32 out + fp16 out (+ecnt zero) ----------------
__global__ void rmsnorm_kernel(const float* __restrict__ Xext, int xid, int yid, int hid,
                               const float* __restrict__ W)
{
    if (blockIdx.x == 0 && threadIdx.x < NE) g_ecnt[threadIdx.x] = 0;
    const float* X = resolve_buf(xid, Xext);
    float*       Y = (yid >= 0) ? resolve_buf(yid, nullptr) : nullptr;
    __half*      Yh = resolve_hbuf(hid);
    int t = blockIdx.x;
    const float* x = X + (size_t)t*DMODEL;
    float s = 0.f;
    for (int i = threadIdx.x; i < DMODEL; i += 256) { float v = x[i]; s += v*v; }
    for (int o = 16; o; o >>= 1) s += __shfl_down_sync(0xffffffffu, s, o);
    __shared__ float red[8];
    __shared__ float scl;
    if ((threadIdx.x & 31) == 0) red[threadIdx.x >> 5] = s;
    __syncthreads();
    if (threadIdx.x == 0) {
        float tot = 0.f;
        #pragma unroll
        for (int i = 0; i < 8; i++) tot += red[i];
        scl = rsqrtf(tot * (1.0f/DMODEL) + 1e-6f);
    }
    __syncthreads();
    float sc = scl;
    __half* yh = Yh + (size_t)t*DMODEL;
    for (int i = threadIdx.x; i < DMODEL; i += 256) {
        float v = x[i]*sc*W[i];
        if (Y) Y[(size_t)t*DMODEL + i] = v;
        yh[i] = __float2half_rn(v);
    }
}

// ---------------- fused QKV GEMM with RoPE epilogue ----------------
// blockIdx.z: 0 -> Q (rope), 1 -> K (rope), 2 -> V (no rope)
__global__ void __launch_bounds__(256, 2) gemm_qkv(const float* __restrict__ Cs,
                                                   const float* __restrict__ Sn)
{
    const int z = blockIdx.z;
    const __half* A = g_qn16;
    const __half* B = (z == 0) ? g_wq16 : (z == 1) ? g_wk16 : g_wv16;
    __half*       C = (z == 0) ? g_q16  : (z == 1) ? g_k16  : g_v16;
    const int Kd = DMODEL, N = DMODEL;

    __shared__ __half As[2][128*64];
    __shared__ __half Bs[2][128*64];

    const int tid  = threadIdx.x;
    const int m0   = blockIdx.y * 128, n0 = blockIdx.x * 128;
    const int warp = tid >> 5, lane = tid & 31;
    const int wm   = (warp & 3) * 32;
    const int wn   = (warp >> 2) * 64;
    const int g    = lane >> 2, tg = lane & 3;

    const uint32_t sA = (uint32_t)__cvta_generic_to_shared(&As[0][0]);
    const uint32_t sB = (uint32_t)__cvta_generic_to_shared(&Bs[0][0]);

    float c[2][8][4];
    #pragma unroll
    for (int i = 0; i < 2; i++)
        #pragma unroll
        for (int j = 0; j < 8; j++)
            #pragma unroll
            for (int r = 0; r < 4; r++) c[i][j][r] = 0.f;

    const int nkt = Kd >> 6;

    #define ISSUE_QKV(s, k0)                                                       \
    {                                                                              \
        _Pragma("unroll")                                                          \
        for (int p = 0; p < 4; p++) {                                              \
            int lin = tid + p*256;                                                 \
            int row = lin >> 3, ch = lin & 7;                                      \
            uint32_t so = ((s)*8192 + row*64 + ((ch ^ (row & 7)) << 3)) * 2;       \
            CP16(sA + so, A + (size_t)(m0+row)*Kd + (k0) + ch*8);                  \
            CP16(sB + so, B + (size_t)(n0+row)*Kd + (k0) + ch*8);                  \
        }                                                                          \
    }

    ISSUE_QKV(0, 0);
    CPCOMMIT();

    for (int kt = 0; kt < nkt; kt++) {
        if (kt + 1 < nkt) {
            ISSUE_QKV((kt+1) & 1, (kt+1) << 6);
            CPCOMMIT();
            CPWAIT(1);
        } else {
            CPWAIT(0);
        }
        __syncthreads();

        const uint32_t asb = sA + (kt & 1)*16384;
        const uint32_t bsb = sB + (kt & 1)*16384;
        #pragma unroll
        for (int ks = 0; ks < 4; ks++) {
            uint32_t a[2][4], b[8][2];
            ldsm_a(a[0], asb, wm,      ks, lane);
            ldsm_a(a[1], asb, wm + 16, ks, lane);
            ldsm_b2(b[0], b[1], bsb, wn,      ks, lane);
            ldsm_b2(b[2], b[3], bsb, wn + 16, ks, lane);
            ldsm_b2(b[4], b[5], bsb, wn + 32, ks, lane);
            ldsm_b2(b[6], b[7], bsb, wn + 48, ks, lane);
            #pragma unroll
            for (int i = 0; i < 2; i++)
                #pragma unroll
                for (int j = 0; j < 8; j++) mma_f16(c[i][j], a[i], b[j]);
        }
        __syncthreads();
    }

    const bool do_rope = (z < 2);
    #pragma unroll
    for (int i = 0; i < 2; i++) {
        int r0 = m0 + wm + i*16 + g;
        int r1 = r0 + 8;
        int s0 = r0 & (SEQ-1), s1 = r1 & (SEQ-1);
        #pragma unroll
        for (int j = 0; j < 8; j++) {
            int cb = n0 + wn + j*8 + tg*2;
            float2 v0 = {c[i][j][0], c[i][j][1]};
            float2 v1 = {c[i][j][2], c[i][j][3]};
            if (do_rope) {
                int p = (cb & 63) >> 1;
                float c0 = Cs[s0*32 + p], n0r = Sn[s0*32 + p];
                float c1v = Cs[s1*32 + p], n1r = Sn[s1*32 + p];
                v0 = {v0.x*c0 - v0.y*n0r, v0.x*n0r + v0.y*c0};
                v1 = {v1.x*c1v - v1.y*n1r, v1.x*n1r + v1.y*c1v};
            }
            *(__half2*)&C[(size_t)r0*N + cb] = __floats2half2_rn(v0.x, v0.y);
            *(__half2*)&C[(size_t)r1*N + cb] = __floats2half2_rn(v1.x, v1.y);
        }
    }
}

// ---------------- dense fp16 NT GEMM (used for WO): 128x128, BK=64, 2-stage ----------------
__global__ void __launch_bounds__(256, 2) gemm_h(int aid, int bid, int cid, int hid,
                                                 const float* __restrict__ Rext, int has_r,
                                                 int N, int Kd)
{
    const __half* A = resolve_hbuf(aid);
    const __half* B = resolve_hbuf(bid);

    __shared__ __half As[2][128*64];
    __shared__ __half Bs[2][128*64];

    const int tid  = threadIdx.x;
    const int m0   = blockIdx.y * 128, n0 = blockIdx.x * 128;
    const int warp = tid >> 5, lane = tid & 31;
    const int wm   = (warp & 3) * 32;
    const int wn   = (warp >> 2) * 64;
    const int g    = lane >> 2, tg = lane & 3;

    const uint32_t sA = (uint32_t)__cvta_generic_to_shared(&As[0][0]);
    const uint32_t sB = (uint32_t)__cvta_generic_to_shared(&Bs[0][0]);

    float c[2][8][4];
    #pragma unroll
    for (int i = 0; i < 2; i++)
        #pragma unroll
        for (int j = 0; j < 8; j++)
            #pragma unroll
            for (int r = 0; r < 4; r++) c[i][j][r] = 0.f;

    const int nkt = Kd >> 6;

    #define ISSUE_DENSE(s, k0)                                                     \
    {                                                                              \
        _Pragma("unroll")                                                          \
        for (int p = 0; p < 4; p++) {                                              \
            int lin = tid + p*256;                                                 \
            int row = lin >> 3, ch = lin & 7;                                      \
            uint32_t so = ((s)*8192 + row*64 + ((ch ^ (row & 7)) << 3)) * 2;       \
            CP16(sA + so, A + (size_t)(m0+row)*Kd + (k0) + ch*8);                  \
            CP16(sB + so, B + (size_t)(n0+row)*Kd + (k0) + ch*8);                  \
        }                                                                          \
    }

    ISSUE_DENSE(0, 0);
    CPCOMMIT();

    for (int kt = 0; kt < nkt; kt++) {
        if (kt + 1 < nkt) {
            ISSUE_DENSE((kt+1) & 1, (kt+1) << 6);
            CPCOMMIT();
            CPWAIT(1);
        } else {
            CPWAIT(0);
        }
        __syncthreads();

        const uint32_t asb = sA + (kt & 1)*16384;
        const uint32_t bsb = sB + (kt & 1)*16384;
        #pragma unroll
        for (int ks = 0; ks < 4; ks++) {
            uint32_t a[2][4], b[8][2];
            ldsm_a(a[0], asb, wm,      ks, lane);
            ldsm_a(a[1], asb, wm + 16, ks, lane);
            ldsm_b2(b[0], b[1], bsb, wn,      ks, lane);
            ldsm_b2(b[2], b[3], bsb, wn + 16, ks, lane);
            ldsm_b2(b[4], b[5], bsb, wn + 32, ks, lane);
            ldsm_b2(b[6], b[7], bsb, wn + 48, ks, lane);
            #pragma unroll
            for (int i = 0; i < 2; i++)
                #pragma unroll
                for (int j = 0; j < 8; j++) mma_f16(c[i][j], a[i], b[j]);
        }
        __syncthreads();
    }

    if (cid >= 0) {
        float* C = resolve_buf(cid, nullptr);
        #pragma unroll
        for (int i = 0; i < 2; i++) {
            int r0 = m0 + wm + i*16 + g;
            int r1 = r0 + 8;
            #pragma unroll
            for (int j = 0; j < 8; j++) {
                int cb = n0 + wn + j*8 + tg*2;
                float2 v0 = {c[i][j][0], c[i][j][1]};
                float2 v1 = {c[i][j][2], c[i][j][3]};
                if (has_r) {
                    const float2 ra = *(const float2*)&Rext[(size_t)r0*N + cb];
                    const float2 rb = *(const float2*)&Rext[(size_t)r1*N + cb];
                    v0.x += ra.x; v0.y += ra.y; v1.x += rb.x; v1.y += rb.y;
                }
                *(float2*)&C[(size_t)r0*N + cb] = v0;
                *(float2*)&C[(size_t)r1*N + cb] = v1;
            }
        }
    } else {
        __half* C = resolve_hbuf(hid);
        #pragma unroll
        for (int i = 0; i < 2; i++) {
            int r0 = m0 + wm + i*16 + g;
            int r1 = r0 + 8;
            #pragma unroll
            for (int j = 0; j < 8; j++) {
                int cb = n0 + wn + j*8 + tg*2;
                *(__half2*)&C[(size_t)r0*N + cb] = __floats2half2_rn(c[i][j][0], c[i][j][1]);
                *(__half2*)&C[(size_t)r1*N + cb] = __floats2half2_rn(c[i][j][2], c[i][j][3]);
            }
        }
    }
}

// ---------------- fused w1||w3 gathered GEMM -> hg16 = silu(x@w1^T) * (x@w3^T) ----------------
__global__ void __launch_bounds__(256, 2) gemm_w13()
{
    const int e  = blockIdx.z;
    const int ne = g_ecnt[e];
    const int m0 = blockIdx.y * 128;
    if (m0 >= ne) return;
    const int n0 = blockIdx.x * 64;

    const __half* B1 = g_w1h + (size_t)e*FF*DMODEL;
    const __half* B3 = g_w3h + (size_t)e*FF*DMODEL;
    const int* list = g_elist + e*TOK;

    __shared__ __half As [2][128*64];
    __shared__ __half B1s[2][64*64];
    __shared__ __half B3s[2][64*64];
    __shared__ int rslot[128];

    const int tid = threadIdx.x;
    if (tid < 128) {
        int m = m0 + tid;
        rslot[tid] = (m < ne) ? list[m] : -1;
    }
    __syncthreads();

    const int warp = tid >> 5, lane = tid & 31;
    const int wm   = (warp & 3) * 32;
    const int wn   = (warp >> 2) * 32;
    const int g    = lane >> 2, tg = lane & 3;

    const uint32_t sA  = (uint32_t)__cvta_generic_to_shared(&As[0][0]);
    const uint32_t sB1 = (uint32_t)__cvta_generic_to_shared(&B1s[0][0]);
    const uint32_t sB3 = (uint32_t)__cvta_generic_to_shared(&B3s[0][0]);

    int arow[4];
    #pragma unroll
    for (int p = 0; p < 4; p++) {
        int sl = rslot[(tid + p*256) >> 3];
        arow[p] = (sl < 0) ? 0 : (sl >> 1);
    }

    float c1[2][4][4], c3[2][4][4];
    #pragma unroll
    for (int i = 0; i < 2; i++)
        #pragma unroll
        for (int j = 0; j < 4; j++)
            #pragma unroll
            for (int r = 0; r < 4; r++) { c1[i][j][r] = 0.f; c3[i][j][r] = 0.f; }

    const int nkt = DMODEL >> 6;

    #define ISSUE_W13(s, k0)                                                       \
    {                                                                              \
        _Pragma("unroll")                                                          \
        for (int p = 0; p < 4; p++) {                                              \
            int lin = tid + p*256;                                                 \
            int row = lin >> 3, ch = lin & 7;                                      \
            uint32_t so = ((s)*8192 + row*64 + ((ch ^ (row & 7)) << 3)) * 2;       \
            CP16(sA + so, g_hn16 + (size_t)arow[p]*DMODEL + (k0) + ch*8);          \
        }                                                                          \
        _Pragma("unroll")                                                          \
        for (int p = 0; p < 2; p++) {                                              \
            int lin = tid + p*256;                                                 \
            int row = lin >> 3, ch = lin & 7;                                      \
            uint32_t so = ((s)*4096 + row*64 + ((ch ^ (row & 7)) << 3)) * 2;       \
            CP16(sB1 + so, B1 + (size_t)(n0+row)*DMODEL + (k0) + ch*8);            \
            CP16(sB3 + so, B3 + (size_t)(n0+row)*DMODEL + (k0) + ch*8);            \
        }                                                                          \
    }

    ISSUE_W13(0, 0);
    CPCOMMIT();

    for (int kt = 0; kt < nkt; kt++) {
        if (kt + 1 < nkt) {
            ISSUE_W13((kt+1) & 1, (kt+1) << 6);
            CPCOMMIT();
            CPWAIT(1);
        } else {
            CPWAIT(0);
        }
        __syncthreads();

        const uint32_t asb  = sA  + (kt & 1)*16384;
        const uint32_t b1sb = sB1 + (kt & 1)*8192;
        const uint32_t b3sb = sB3 + (kt & 1)*8192;
        #pragma unroll
        for (int ks = 0; ks < 4; ks++) {
            uint32_t a[2][4], b1[4][2], b3[4][2];
            ldsm_a(a[0], asb, wm,      ks, lane);
            ldsm_a(a[1], asb, wm + 16, ks, lane);
            ldsm_b2(b1[0], b1[1], b1sb, wn,      ks, lane);
            ldsm_b2(b1[2], b1[3], b1sb, wn + 16, ks, lane);
            ldsm_b2(b3[0], b3[1], b3sb, wn,      ks, lane);
            ldsm_b2(b3[2], b3[3], b3sb, wn + 16, ks, lane);
            #pragma unroll
            for (int i = 0; i < 2; i++)
                #pragma unroll
                for (int j = 0; j < 4; j++) {
                    mma_f16(c1[i][j], a[i], b1[j]);
                    mma_f16(c3[i][j], a[i], b3[j]);
                }
        }
        __syncthreads();
    }

    #pragma unroll
    for (int i = 0; i < 2; i++) {
        int l0 = wm + i*16 + g;
        int l1 = l0 + 8;
        int s0 = rslot[l0], s1 = rslot[l1];
        #pragma unroll
        for (int j = 0; j < 4; j++) {
            int cb = n0 + wn + j*8 + tg*2;
            if (s0 >= 0) {
                float t1x = c1[i][j][0], t1y = c1[i][j][1];
                float x0 = t1x/(1.f + __expf(-t1x)) * c3[i][j][0];
                float x1 = t1y/(1.f + __expf(-t1y)) * c3[i][j][1];
                *(__half2*)&g_hg16[(size_t)s0*FF + cb] = __floats2half2_rn(x0, x1);
            }
            if (s1 >= 0) {
                float t1x = c1[i][j][2], t1y = c1[i][j][3];
                float x0 = t1x/(1.f + __expf(-t1x)) * c3[i][j][2];
                float x1 = t1y/(1.f + __expf(-t1y)) * c3[i][j][3];
                *(__half2*)&g_hg16[(size_t)s1*FF + cb] = __floats2half2_rn(x0, x1);
            }
        }
    }
}

// ---------------- gathered fp16 NT GEMM for MoE w2 pass (fp32 out) ----------------
__global__ void __launch_bounds__(256, 2) gemm_h_gather(int asel, int bid, size_t strideB,
                                                        int cid, int N, int Kd)
{
    const int e  = blockIdx.z;
    const int ne = g_ecnt[e];
    const int m0 = blockIdx.y * 128;
    if (m0 >= ne) return;
    const int n0 = blockIdx.x * 128;

    const __half* A = (asel == 0) ? g_hn16 : g_hg16;
    const __half* B = resolve_hbuf(bid) + (size_t)e * strideB;
    const int* list = g_elist + e*TOK;

    __shared__ __half As[2][128*64];
    __shared__ __half Bs[2][128*64];
    __shared__ int rslot[128];

    const int tid = threadIdx.x;
    if (tid < 128) {
        int m = m0 + tid;
        rslot[tid] = (m < ne) ? list[m] : -1;
    }
    __syncthreads();

    const int warp = tid >> 5, lane = tid & 31;
    const int wm   = (warp & 3) * 32;
    const int wn   = (warp >> 2) * 64;
    const int g    = lane >> 2, tg = lane & 3;

    const uint32_t sA = (uint32_t)__cvta_generic_to_shared(&As[0][0]);
    const uint32_t sB = (uint32_t)__cvta_generic_to_shared(&Bs[0][0]);

    int arow[4];
    #pragma unroll
    for (int p = 0; p < 4; p++) {
        int lin = tid + p*256;
        int sl  = rslot[lin >> 3];
        arow[p] = (sl < 0) ? 0 : ((asel == 0) ? (sl >> 1) : sl);
    }

    float c[2][8][4];
    #pragma unroll
    for (int i = 0; i < 2; i++)
        #pragma unroll
        for (int j = 0; j < 8; j++)
            #pragma unroll
            for (int r = 0; r < 4; r++) c[i][j][r] = 0.f;

    const int nkt = Kd >> 6;

    #define ISSUE_GATHER(s, k0)                                                    \
    {                                                                              \
        _Pragma("unroll")                                                          \
        for (int p = 0; p < 4; p++) {                                              \
            int lin = tid + p*256;                                                 \
            int row = lin >> 3, ch = lin & 7;                                      \
            uint32_t so = ((s)*8192 + row*64 + ((ch ^ (row & 7)) << 3)) * 2;       \
            CP16(sA + so, A + (size_t)arow[p]*Kd + (k0) + ch*8);                   \
            CP16(sB + so, B + (size_t)(n0+row)*Kd + (k0) + ch*8);                  \
        }                                                                          \
    }

    ISSUE_GATHER(0, 0);
    CPCOMMIT();

    for (int kt = 0; kt < nkt; kt++) {
        if (kt + 1 < nkt) {
            ISSUE_GATHER((kt+1) & 1, (kt+1) << 6);
            CPCOMMIT();
            CPWAIT(1);
        } else {
            CPWAIT(0);
        }
        __syncthreads();

        const uint32_t asb = sA + (kt & 1)*16384;
        const uint32_t bsb = sB + (kt & 1)*16384;
        #pragma unroll
        for (int ks = 0; ks < 4; ks++) {
            uint32_t a[2][4], b[8][2];
            ldsm_a(a[0], asb, wm,      ks, lane);
            ldsm_a(a[1], asb, wm + 16, ks, lane);
            ldsm_b2(b[0], b[1], bsb, wn,      ks, lane);
            ldsm_b2(b[2], b[3], bsb, wn + 16, ks, lane);
            ldsm_b2(b[4], b[5], bsb, wn + 32, ks, lane);
            ldsm_b2(b[6], b[7], bsb, wn + 48, ks, lane);
            #pragma unroll
            for (int i = 0; i < 2; i++)
                #pragma unroll
                for (int j = 0; j < 8; j++) mma_f16(c[i][j], a[i], b[j]);
        }
        __syncthreads();
    }

    float* C = resolve_buf(cid, nullptr);
    #pragma unroll
    for (int i = 0; i < 2; i++) {
        int l0 = wm + i*16 + g;
        int l1 = l0 + 8;
        int s0 = rslot[l0], s1 = rslot[l1];
        #pragma unroll
        for (int j = 0; j < 8; j++) {
            int cb = n0 + wn + j*8 + tg*2;
            if (s0 >= 0) { float2 v = {c[i][j][0], c[i][j][1]}; *(float2*)&C[(size_t)s0*N + cb] = v; }
            if (s1 >= 0) { float2 v = {c[i][j][2], c[i][j][3]}; *(float2*)&C[(size_t)s1*N + cb] = v; }
        }
    }
}

// ---------------- tensor-core flash attention ----------------
__global__ void __launch_bounds__(128) flash16_kernel(const int* __restrict__ causal_p)
{
    __shared__ __half Qs[64*64];
    __shared__ __half Ks[64*64];
    __shared__ __half Vt[64*72];   // transposed [d][j], padded rows

    const int b  = blockIdx.z;
    const int hh = blockIdx.y;
    const int q0 = blockIdx.x * 64;
    const int t  = threadIdx.x;
    const int warp = t >> 5, lane = t & 31;
    const int g = lane >> 2, tg = lane & 3;

    const uint32_t sQ = (uint32_t)__cvta_generic_to_shared(Qs);
    const uint32_t sK = (uint32_t)__cvta_generic_to_shared(Ks);

    size_t qgbase = ((size_t)(b*SEQ + q0))*DMODEL + hh*HDIM;
    #pragma unroll
    for (int p = 0; p < 4; p++) {
        int lin = t + p*128;
        int row = lin >> 3, ch = lin & 7;
        uint32_t so = (row*64 + ((ch ^ (row & 7)) << 3)) * 2;
        CP16(sQ + so, g_q16 + qgbase + (size_t)row*DMODEL + ch*8);
    }
    CPCOMMIT();

    const int causal = *causal_p;
    const int kend = causal ? (q0 + 64) : SEQ;

    float m0 = -3.4e38f, m1 = -3.4e38f, l0 = 0.f, l1 = 0.f;
    float co[8][4];
    #pragma unroll
    for (int j = 0; j < 8; j++)
        #pragma unroll
        for (int r = 0; r < 4; r++) co[j][r] = 0.f;

    CPWAIT(0);
    __syncthreads();

    for (int k0 = 0; k0 < kend; k0 += 64) {
        size_t kgbase = ((size_t)(b*SEQ + k0))*DMODEL + hh*HDIM;
        #pragma unroll
        for (int p = 0; p < 4; p++) {
            int lin = t + p*128;
            int row = lin >> 3, ch = lin & 7;
            uint32_t so = (row*64 + ((ch ^ (row & 7)) << 3)) * 2;
            CP16(sK + so, g_k16 + kgbase + (size_t)row*DMODEL + ch*8);
        }
        CPCOMMIT();
        #pragma unroll
        for (int p = 0; p < 4; p++) {
            int lin = t + p*128;
            int row = lin >> 3, ch = lin & 7;
            uint4 v = *(const uint4*)(g_v16 + kgbase + (size_t)row*DMODEL + ch*8);
            const __half* hv = (const __half*)&v;
            #pragma unroll
            for (int i = 0; i < 8; i++) Vt[(ch*8 + i)*72 + row] = hv[i];
        }
        CPWAIT(0);
        __syncthreads();

        float s[8][4];
        #pragma unroll
        for (int j = 0; j < 8; j++)
            #pragma unroll
            for (int r = 0; r < 4; r++) s[j][r] = 0.f;

        #pragma unroll
        for (int ks = 0; ks < 4; ks++) {
            uint32_t a[4];
            ldsm_a(a, sQ, warp*16, ks, lane);
            #pragma unroll
            for (int jp = 0; jp < 4; jp++) {
                uint32_t bb0[2], bb1[2];
                ldsm_b2(bb0, bb1, sK, 16*jp, ks, lane);
                mma_f16(s[2*jp  ], a, bb0);
                mma_f16(s[2*jp+1], a, bb1);
            }
        }

        const int row0 = q0 + warp*16 + g;
        const int row1 = row0 + 8;
        const bool maskt = causal && (k0 == q0);
        float mx0 = -3.4e38f, mx1 = -3.4e38f;
        #pragma unroll
        for (int j = 0; j < 8; j++) {
            int c0 = k0 + 8*j + 2*tg, c1 = c0 + 1;
            s[j][0] *= 0.125f; s[j][1] *= 0.125f; s[j][2] *= 0.125f; s[j][3] *= 0.125f;
            if (maskt) {
                if (c0 > row0) s[j][0] = -1e30f;
                if (c1 > row0) s[j][1] = -1e30f;
                if (c0 > row1) s[j][2] = -1e30f;
                if (c1 > row1) s[j][3] = -1e30f;
            }
            mx0 = fmaxf(mx0, fmaxf(s[j][0], s[j][1]));
            mx1 = fmaxf(mx1, fmaxf(s[j][2], s[j][3]));
        }
        mx0 = fmaxf(mx0, __shfl_xor_sync(0xffffffffu, mx0, 1));
        mx0 = fmaxf(mx0, __shfl_xor_sync(0xffffffffu, mx0, 2));
        mx1 = fmaxf(mx1, __shfl_xor_sync(0xffffffffu, mx1, 1));
        mx1 = fmaxf(mx1, __shfl_xor_sync(0xffffffffu, mx1, 2));

        float mn0 = fmaxf(m0, mx0), mn1 = fmaxf(m1, mx1);
        float al0 = __expf(m0 - mn0), al1 = __expf(m1 - mn1);
        float sm0 = 0.f, sm1 = 0.f;
        #pragma unroll
        for (int j = 0; j < 8; j++) {
            s[j][0] = __expf(s[j][0] - mn0);
            s[j][1] = __expf(s[j][1] - mn0);
            s[j][2] = __expf(s[j][2] - mn1);
            s[j][3] = __expf(s[j][3] - mn1);
            sm0 += s[j][0] + s[j][1];
            sm1 += s[j][2] + s[j][3];
        }
        sm0 += __shfl_xor_sync(0xffffffffu, sm0, 1);
        sm0 += __shfl_xor_sync(0xffffffffu, sm0, 2);
        sm1 += __shfl_xor_sync(0xffffffffu, sm1, 1);
        sm1 += __shfl_xor_sync(0xffffffffu, sm1, 2);

        l0 = l0*al0 + sm0; l1 = l1*al1 + sm1;
        m0 = mn0; m1 = mn1;

        #pragma unroll
        for (int j = 0; j < 8; j++) {
            co[j][0] *= al0; co[j][1] *= al0;
            co[j][2] *= al1; co[j][3] *= al1;
        }

        #pragma unroll
        for (int ks = 0; ks < 4; ks++) {
            uint32_t a[4];
            a[0] = packh2(s[2*ks  ][0], s[2*ks  ][1]);
            a[1] = packh2(s[2*ks  ][2], s[2*ks  ][3]);
            a[2] = packh2(s[2*ks+1][0], s[2*ks+1][1]);
            a[3] = packh2(s[2*ks+1][2], s[2*ks+1][3]);
            #pragma unroll
            for (int db = 0; db < 8; db++) {
                uint32_t bb[2];
                bb[0] = *(const uint32_t*)&Vt[(8*db + g)*72 + ks*16     + 2*tg];
                bb[1] = *(const uint32_t*)&Vt[(8*db + g)*72 + ks*16 + 8 + 2*tg];
                mma_f16(co[db], a, bb);
            }
        }
        __syncthreads();
    }

    float inv0 = 1.f/l0, inv1 = 1.f/l1;
    size_t ob0 = ((size_t)(b*SEQ + q0 + warp*16 + g))*DMODEL + hh*HDIM;
    size_t ob1 = ob0 + (size_t)8*DMODEL;
    #pragma unroll
    for (int db = 0; db < 8; db++) {
        *(__half2*)&g_ctx16[ob0 + 8*db + 2*tg] = __floats2half2_rn(co[db][0]*inv0, co[db][1]*inv0);
        *(__half2*)&g_ctx16[ob1 + 8*db + 2*tg] = __floats2half2_rn(co[db][2]*inv1, co[db][3]*inv1);
    }
}

// ---------------- router ----------------
__global__ void router_kernel(const float* __restrict__ RW, const float* __restrict__ RB)
{
    int t = blockIdx.x;
    int e = threadIdx.x >> 4;
    int l = threadIdx.x & 15;
    const float* x = g_hn + (size_t)t*DMODEL;
    const float* w = RW + (size_t)e*DMODEL;
    float s = 0.f;
    for (int i = l; i < DMODEL; i += 16) s += x[i]*w[i];
    #pragma unroll
    for (int o = 8; o; o >>= 1) s += __shfl_down_sync(0xffffffffu, s, o, 16);
    __shared__ float lg[NE];
    if (l == 0) lg[e] = s + RB[e];
    __syncthreads();
    if (threadIdx.x == 0) {
        int i0 = 0; float v0 = lg[0];
        #pragma unroll
        for (int i = 1; i < NE; i++) if (lg[i] > v0) { v0 = lg[i]; i0 = i; }
        int i1 = -1; float v1 = -3.4e38f;
        #pragma unroll
        for (int i = 0; i < NE; i++) if (i != i0 && lg[i] > v1) { v1 = lg[i]; i1 = i; }
        float ex = __expf(v1 - v0);
        float p0 = 1.f/(1.f + ex);
        float p1 = ex/(1.f + ex);
        int s0 = t*2, s1 = t*2 + 1;
        int pos0 = atomicAdd(&g_ecnt[i0], 1); g_elist[i0*TOK + pos0] = s0;
        int pos1 = atomicAdd(&g_ecnt[i1], 1); g_elist[i1*TOK + pos1] = s1;
        g_gate[s0] = p0;
        g_gate[s1] = p1;
    }
}

// ---------------- final residual combine ----------------
__global__ void final_kernel(float* __restrict__ out)
{
    int idx = blockIdx.x*256 + threadIdx.x;
    if (idx >= TOK*DMODEL) return;
    int tok = idx >> 10, d = idx & 1023;
    out[idx] = g_h[idx]
             + g_gate[tok*2    ] * g_y2[(size_t)(tok*2    )*DMODEL + d]
             + g_gate[tok*2 + 1] * g_y2[(size_t)(tok*2 + 1)*DMODEL + d];
}

// ---------------- host launcher ----------------
extern "C" void kernel_launch(void* const* d_in, const int* in_sizes, int n_in,
                              void* d_out, int out_size)
{
    const float* q    = (const float*)d_in[0];
    const float* fc   = (const float*)d_in[3];
    const float* fs   = (const float*)d_in[4];
    const float* anw  = (const float*)d_in[5];
    const float* fnw  = (const float*)d_in[6];
    const float* wq   = (const float*)d_in[7];
    const float* wk   = (const float*)d_in[8];
    const float* wv   = (const float*)d_in[9];
    const float* wo   = (const float*)d_in[10];
    const float* rw   = (const float*)d_in[11];
    const float* rb   = (const float*)d_in[12];
    const float* w1   = (const float*)d_in[13];
    const float* w2   = (const float*)d_in[14];
    const float* w3   = (const float*)d_in[15];
    const int*   cz   = (const int*)d_in[16];
    float* out = (float*)d_out;

    // all weight conversions in one launch
    {
        size_t total4 = (size_t)4*DMODEL*DMODEL/4 + (size_t)3*NE*FF*DMODEL/4;
        int blocks = (int)((total4 + 255)/256);
        f2h_all<<<blocks, 256>>>((const float4*)wq, (const float4*)wk, (const float4*)wv,
                                 (const float4*)wo, (const float4*)w1, (const float4*)w3,
                                 (const float4*)w2);
    }

    rmsnorm_kernel<<<TOK, 256>>>(q, BUF_EXT, -1, HB_QN16, anw);

    // fused QKV projections + RoPE epilogue
    gemm_qkv<<<dim3(DMODEL/128, TOK/128, 3), 256>>>(fc, fs);

    flash16_kernel<<<dim3(SEQ/64, NH, 4), 128>>>(cz);

    dim3 gproj(DMODEL/128, TOK/128);
    gemm_h<<<gproj, 256>>>(HB_CTX16, HB_WO, BUF_H, 0, q, 1, DMODEL, DMODEL);

    rmsnorm_kernel<<<TOK, 256>>>(nullptr, BUF_H, BUF_HN, HB_HN16, fnw);

    router_kernel<<<TOK, 128>>>(rw, rb);

    // fused w1||w3 -> hg16 (silu applied in epilogue)
    gemm_w13<<<dim3(FF/64, TOK/128, NE), 256>>>();

    // w2 pass -> y2 (fp32)
    gemm_h_gather<<<dim3(DMODEL/128, TOK/128, NE), 256>>>(1, HB_W2, (size_t)DMODEL*FF, BUF_Y2, DMODEL, FF);

    final_kernel<<<(TOK*DMODEL + 255)/256, 256>>>(out);
}

// round 16
// speedup vs baseline: 1.3434x; 1.3434x over previous
#include <cuda_runtime.h>
#include <cuda_fp16.h>
#include <cstdint>

#define TOK    4096   // B*S
#define DMODEL 1024
#define NH     16
#define HDIM   64
#define NE     8
#define FF     4096
#define SEQ    1024

// ---------------- scratch (device globals) ----------------
__device__ float  g_h  [TOK*DMODEL];
__device__ float  g_hn [TOK*DMODEL];
__device__ float  g_y2 [(size_t)2*TOK*DMODEL];
__device__ int    g_ecnt[NE];
__device__ int    g_elist[NE*TOK];
__device__ float  g_gate[2*TOK];

// fp16 buffers
__device__ __half g_qn16 [TOK*DMODEL];
__device__ __half g_ctx16[TOK*DMODEL];
__device__ __half g_hn16 [TOK*DMODEL];
__device__ __half g_hg16 [(size_t)2*TOK*FF];
__device__ __half g_q16  [TOK*DMODEL];
__device__ __half g_k16  [TOK*DMODEL];
__device__ __half g_v16  [TOK*DMODEL];
__device__ __half g_wq16 [DMODEL*DMODEL];
__device__ __half g_wk16 [DMODEL*DMODEL];
__device__ __half g_wv16 [DMODEL*DMODEL];
__device__ __half g_wo16 [DMODEL*DMODEL];
__device__ __half g_w1h  [(size_t)NE*FF*DMODEL];
__device__ __half g_w3h  [(size_t)NE*FF*DMODEL];
__device__ __half g_w2h  [(size_t)NE*DMODEL*FF];

// fp32 buf ids
#define BUF_H   0
#define BUF_HN  1
#define BUF_Y2  2
#define BUF_EXT (-1)

__device__ __forceinline__ float* resolve_buf(int id, const float* ext) {
    switch (id) {
        case BUF_H:   return g_h;
        case BUF_HN:  return g_hn;
        case BUF_Y2:  return g_y2;
    }
    return (float*)ext;
}

// half buf ids
#define HB_QN16  0
#define HB_CTX16 1
#define HB_HN16  2
#define HB_HG16  3
#define HB_WO    7
#define HB_W2    10

__device__ __forceinline__ __half* resolve_hbuf(int id) {
    switch (id) {
        case HB_QN16:  return g_qn16;
        case HB_CTX16: return g_ctx16;
        case HB_HN16:  return g_hn16;
        case HB_HG16:  return g_hg16;
        case HB_WO:    return g_wo16;
        case HB_W2:    return g_w2h;
    }
    return g_qn16;
}

// ---------------- helpers ----------------
__device__ __forceinline__ void mma_f16(float* c, const uint32_t* a, const uint32_t* b) {
    asm volatile(
        "mma.sync.aligned.m16n8k16.row.col.f32.f16.f16.f32 "
        "{%0,%1,%2,%3}, {%4,%5,%6,%7}, {%8,%9}, {%0,%1,%2,%3};"
        : "+f"(c[0]), "+f"(c[1]), "+f"(c[2]), "+f"(c[3])
        : "r"(a[0]), "r"(a[1]), "r"(a[2]), "r"(a[3]), "r"(b[0]), "r"(b[1]));
}

__device__ __forceinline__ uint32_t packh2(float x, float y) {
    __half2 h = __floats2half2_rn(x, y);
    return *(uint32_t*)&h;
}

#define CP16(dst, src) asm volatile("cp.async.cg.shared.global [%0], [%1], 16;\n" :: "r"(dst), "l"(src))
#define CPCOMMIT()     asm volatile("cp.async.commit_group;\n" ::: "memory")
#define CPWAIT(n)      asm volatile("cp.async.wait_group %0;\n" :: "n"(n) : "memory")

// smem tile: rows x 64 halves (128B rows), 16B-chunk XOR swizzle with row&7
#define LDH(base, row, chunk, off) \
    (*(const uint32_t*)&(base)[(row)*64 + ((((chunk) ^ ((row) & 7)) & 7) << 3) + (off)])

// ---------------- fused f32 -> f16 conversion of all weights ----------------
__global__ void f2h_all(const float4* __restrict__ wq, const float4* __restrict__ wk,
                        const float4* __restrict__ wv, const float4* __restrict__ wo,
                        const float4* __restrict__ w1, const float4* __restrict__ w3,
                        const float4* __restrict__ w2)
{
    const size_t NW  = (size_t)DMODEL*DMODEL/4;   // 2^18
    const size_t NWE = (size_t)NE*FF*DMODEL/4;    // 2^23
    size_t i = (size_t)blockIdx.x*256 + threadIdx.x;
    if (i >= 4*NW + 3*NWE) return;
    const float4* src; __half2* dst; size_t off;
    if (i < 4*NW) {
        int seg = (int)(i >> 18); off = i & (NW - 1);
        src = (seg == 0) ? wq : (seg == 1) ? wk : (seg == 2) ? wv : wo;
        dst = (__half2*)((seg == 0) ? g_wq16 : (seg == 1) ? g_wk16 : (seg == 2) ? g_wv16 : g_wo16);
    } else {
        size_t j = i - 4*NW; int seg = (int)(j >> 23); off = j & (NWE - 1);
        src = (seg == 0) ? w1 : (seg == 1) ? w3 : w2;
        dst = (__half2*)((seg == 0) ? g_w1h : (seg == 1) ? g_w3h : g_w2h);
    }
    float4 v = src[off];
    dst[off*2    ] = __floats2half2_rn(v.x, v.y);
    dst[off*2 + 1] = __floats2half2_rn(v.z, v.w);
}

// ---------------- rmsnorm: optional fp32 out + fp16 out (+ecnt zero) ----------------
__global__ void rmsnorm_kernel(const float* __restrict__ Xext, int xid, int yid, int hid,
                               const float* __restrict__ W)
{
    if (blockIdx.x == 0 && threadIdx.x < NE) g_ecnt[threadIdx.x] = 0;
    const float* X = resolve_buf(xid, Xext);
    float*       Y = (yid >= 0) ? resolve_buf(yid, nullptr) : nullptr;
    __half*      Yh = resolve_hbuf(hid);
    int t = blockIdx.x;
    const float* x = X + (size_t)t*DMODEL;
    float s = 0.f;
    for (int i = threadIdx.x; i < DMODEL; i += 256) { float v = x[i]; s += v*v; }
    for (int o = 16; o; o >>= 1) s += __shfl_down_sync(0xffffffffu, s, o);
    __shared__ float red[8];
    __shared__ float scl;
    if ((threadIdx.x & 31) == 0) red[threadIdx.x >> 5] = s;
    __syncthreads();
    if (threadIdx.x == 0) {
        float tot = 0.f;
        #pragma unroll
        for (int i = 0; i < 8; i++) tot += red[i];
        scl = rsqrtf(tot * (1.0f/DMODEL) + 1e-6f);
    }
    __syncthreads();
    float sc = scl;
    __half* yh = Yh + (size_t)t*DMODEL;
    for (int i = threadIdx.x; i < DMODEL; i += 256) {
        float v = x[i]*sc*W[i];
        if (Y) Y[(size_t)t*DMODEL + i] = v;
        yh[i] = __float2half_rn(v);
    }
}

// ---------------- fused QKV GEMM with RoPE epilogue ----------------
// blockIdx.z: 0 -> Q (rope), 1 -> K (rope), 2 -> V (no rope)
__global__ void __launch_bounds__(256, 2) gemm_qkv(const float* __restrict__ Cs,
                                                   const float* __restrict__ Sn)
{
    const int z = blockIdx.z;
    const __half* A = g_qn16;
    const __half* B = (z == 0) ? g_wq16 : (z == 1) ? g_wk16 : g_wv16;
    __half*       C = (z == 0) ? g_q16  : (z == 1) ? g_k16  : g_v16;
    const int Kd = DMODEL, N = DMODEL;

    __shared__ __half As[2][128*64];
    __shared__ __half Bs[2][128*64];

    const int tid  = threadIdx.x;
    const int m0   = blockIdx.y * 128, n0 = blockIdx.x * 128;
    const int warp = tid >> 5, lane = tid & 31;
    const int wm   = (warp & 3) * 32;
    const int wn   = (warp >> 2) * 64;
    const int g    = lane >> 2, tg = lane & 3;

    const uint32_t sA = (uint32_t)__cvta_generic_to_shared(&As[0][0]);
    const uint32_t sB = (uint32_t)__cvta_generic_to_shared(&Bs[0][0]);

    float c[2][8][4];
    #pragma unroll
    for (int i = 0; i < 2; i++)
        #pragma unroll
        for (int j = 0; j < 8; j++)
            #pragma unroll
            for (int r = 0; r < 4; r++) c[i][j][r] = 0.f;

    const int nkt = Kd >> 6;

    #define ISSUE_QKV(s, k0)                                                       \
    {                                                                              \
        _Pragma("unroll")                                                          \
        for (int p = 0; p < 4; p++) {                                              \
            int lin = tid + p*256;                                                 \
            int row = lin >> 3, ch = lin & 7;                                      \
            uint32_t so = ((s)*8192 + row*64 + ((ch ^ (row & 7)) << 3)) * 2;       \
            CP16(sA + so, A + (size_t)(m0+row)*Kd + (k0) + ch*8);                  \
            CP16(sB + so, B + (size_t)(n0+row)*Kd + (k0) + ch*8);                  \
        }                                                                          \
    }

    ISSUE_QKV(0, 0);
    CPCOMMIT();

    for (int kt = 0; kt < nkt; kt++) {
        if (kt + 1 < nkt) {
            ISSUE_QKV((kt+1) & 1, (kt+1) << 6);
            CPCOMMIT();
            CPWAIT(1);
        } else {
            CPWAIT(0);
        }
        __syncthreads();

        const __half* as = &As[kt & 1][0];
        const __half* bs = &Bs[kt & 1][0];
        #pragma unroll
        for (int ks = 0; ks < 4; ks++) {
            uint32_t a[2][4], b[8][2];
            #pragma unroll
            for (int i = 0; i < 2; i++) {
                int r = wm + i*16 + g;
                a[i][0] = LDH(as, r,     2*ks,   2*tg);
                a[i][1] = LDH(as, r + 8, 2*ks,   2*tg);
                a[i][2] = LDH(as, r,     2*ks+1, 2*tg);
                a[i][3] = LDH(as, r + 8, 2*ks+1, 2*tg);
            }
            #pragma unroll
            for (int j = 0; j < 8; j++) {
                int r = wn + j*8 + g;
                b[j][0] = LDH(bs, r, 2*ks,   2*tg);
                b[j][1] = LDH(bs, r, 2*ks+1, 2*tg);
            }
            #pragma unroll
            for (int i = 0; i < 2; i++)
                #pragma unroll
                for (int j = 0; j < 8; j++) mma_f16(c[i][j], a[i], b[j]);
        }
        __syncthreads();
    }

    const bool do_rope = (z < 2);
    #pragma unroll
    for (int i = 0; i < 2; i++) {
        int r0 = m0 + wm + i*16 + g;
        int r1 = r0 + 8;
        int s0 = r0 & (SEQ-1), s1 = r1 & (SEQ-1);
        #pragma unroll
        for (int j = 0; j < 8; j++) {
            int cb = n0 + wn + j*8 + tg*2;
            float2 v0 = {c[i][j][0], c[i][j][1]};
            float2 v1 = {c[i][j][2], c[i][j][3]};
            if (do_rope) {
                int p = (cb & 63) >> 1;
                float c0 = Cs[s0*32 + p], n0r = Sn[s0*32 + p];
                float c1v = Cs[s1*32 + p], n1r = Sn[s1*32 + p];
                v0 = {v0.x*c0 - v0.y*n0r, v0.x*n0r + v0.y*c0};
                v1 = {v1.x*c1v - v1.y*n1r, v1.x*n1r + v1.y*c1v};
            }
            *(__half2*)&C[(size_t)r0*N + cb] = __floats2half2_rn(v0.x, v0.y);
            *(__half2*)&C[(size_t)r1*N + cb] = __floats2half2_rn(v1.x, v1.y);
        }
    }
}

// ---------------- dense fp16 NT GEMM (used for WO): 128x128, BK=64, 2-stage ----------------
__global__ void __launch_bounds__(256, 2) gemm_h(int aid, int bid, int cid, int hid,
                                                 const float* __restrict__ Rext, int has_r,
                                                 int N, int Kd)
{
    const __half* A = resolve_hbuf(aid);
    const __half* B = resolve_hbuf(bid);

    __shared__ __half As[2][128*64];
    __shared__ __half Bs[2][128*64];

    const int tid  = threadIdx.x;
    const int m0   = blockIdx.y * 128, n0 = blockIdx.x * 128;
    const int warp = tid >> 5, lane = tid & 31;
    const int wm   = (warp & 3) * 32;
    const int wn   = (warp >> 2) * 64;
    const int g    = lane >> 2, tg = lane & 3;

    const uint32_t sA = (uint32_t)__cvta_generic_to_shared(&As[0][0]);
    const uint32_t sB = (uint32_t)__cvta_generic_to_shared(&Bs[0][0]);

    float c[2][8][4];
    #pragma unroll
    for (int i = 0; i < 2; i++)
        #pragma unroll
        for (int j = 0; j < 8; j++)
            #pragma unroll
            for (int r = 0; r < 4; r++) c[i][j][r] = 0.f;

    const int nkt = Kd >> 6;

    #define ISSUE_DENSE(s, k0)                                                     \
    {                                                                              \
        _Pragma("unroll")                                                          \
        for (int p = 0; p < 4; p++) {                                              \
            int lin = tid + p*256;                                                 \
            int row = lin >> 3, ch = lin & 7;                                      \
            uint32_t so = ((s)*8192 + row*64 + ((ch ^ (row & 7)) << 3)) * 2;       \
            CP16(sA + so, A + (size_t)(m0+row)*Kd + (k0) + ch*8);                  \
            CP16(sB + so, B + (size_t)(n0+row)*Kd + (k0) + ch*8);                  \
        }                                                                          \
    }

    ISSUE_DENSE(0, 0);
    CPCOMMIT();

    for (int kt = 0; kt < nkt; kt++) {
        if (kt + 1 < nkt) {
            ISSUE_DENSE((kt+1) & 1, (kt+1) << 6);
            CPCOMMIT();
            CPWAIT(1);
        } else {
            CPWAIT(0);
        }
        __syncthreads();

        const __half* as = &As[kt & 1][0];
        const __half* bs = &Bs[kt & 1][0];
        #pragma unroll
        for (int ks = 0; ks < 4; ks++) {
            uint32_t a[2][4], b[8][2];
            #pragma unroll
            for (int i = 0; i < 2; i++) {
                int r = wm + i*16 + g;
                a[i][0] = LDH(as, r,     2*ks,   2*tg);
                a[i][1] = LDH(as, r + 8, 2*ks,   2*tg);
                a[i][2] = LDH(as, r,     2*ks+1, 2*tg);
                a[i][3] = LDH(as, r + 8, 2*ks+1, 2*tg);
            }
            #pragma unroll
            for (int j = 0; j < 8; j++) {
                int r = wn + j*8 + g;
                b[j][0] = LDH(bs, r, 2*ks,   2*tg);
                b[j][1] = LDH(bs, r, 2*ks+1, 2*tg);
            }
            #pragma unroll
            for (int i = 0; i < 2; i++)
                #pragma unroll
                for (int j = 0; j < 8; j++) mma_f16(c[i][j], a[i], b[j]);
        }
        __syncthreads();
    }

    if (cid >= 0) {
        float* C = resolve_buf(cid, nullptr);
        #pragma unroll
        for (int i = 0; i < 2; i++) {
            int r0 = m0 + wm + i*16 + g;
            int r1 = r0 + 8;
            #pragma unroll
            for (int j = 0; j < 8; j++) {
                int cb = n0 + wn + j*8 + tg*2;
                float2 v0 = {c[i][j][0], c[i][j][1]};
                float2 v1 = {c[i][j][2], c[i][j][3]};
                if (has_r) {
                    const float2 ra = *(const float2*)&Rext[(size_t)r0*N + cb];
                    const float2 rb = *(const float2*)&Rext[(size_t)r1*N + cb];
                    v0.x += ra.x; v0.y += ra.y; v1.x += rb.x; v1.y += rb.y;
                }
                *(float2*)&C[(size_t)r0*N + cb] = v0;
                *(float2*)&C[(size_t)r1*N + cb] = v1;
            }
        }
    } else {
        __half* C = resolve_hbuf(hid);
        #pragma unroll
        for (int i = 0; i < 2; i++) {
            int r0 = m0 + wm + i*16 + g;
            int r1 = r0 + 8;
            #pragma unroll
            for (int j = 0; j < 8; j++) {
                int cb = n0 + wn + j*8 + tg*2;
                *(__half2*)&C[(size_t)r0*N + cb] = __floats2half2_rn(c[i][j][0], c[i][j][1]);
                *(__half2*)&C[(size_t)r1*N + cb] = __floats2half2_rn(c[i][j][2], c[i][j][3]);
            }
        }
    }
}

// ---------------- fused w1||w3 gathered GEMM -> hg16 = silu(x@w1^T) * (x@w3^T) ----------------
__global__ void __launch_bounds__(256, 2) gemm_w13()
{
    const int e  = blockIdx.z;
    const int ne = g_ecnt[e];
    const int m0 = blockIdx.y * 128;
    if (m0 >= ne) return;
    const int n0 = blockIdx.x * 64;

    const __half* B1 = g_w1h + (size_t)e*FF*DMODEL;
    const __half* B3 = g_w3h + (size_t)e*FF*DMODEL;
    const int* list = g_elist + e*TOK;

    __shared__ __half As [2][128*64];
    __shared__ __half B1s[2][64*64];
    __shared__ __half B3s[2][64*64];
    __shared__ int rslot[128];

    const int tid = threadIdx.x;
    if (tid < 128) {
        int m = m0 + tid;
        rslot[tid] = (m < ne) ? list[m] : -1;
    }
    __syncthreads();

    const int warp = tid >> 5, lane = tid & 31;
    const int wm   = (warp & 3) * 32;
    const int wn   = (warp >> 2) * 32;
    const int g    = lane >> 2, tg = lane & 3;

    const uint32_t sA  = (uint32_t)__cvta_generic_to_shared(&As[0][0]);
    const uint32_t sB1 = (uint32_t)__cvta_generic_to_shared(&B1s[0][0]);
    const uint32_t sB3 = (uint32_t)__cvta_generic_to_shared(&B3s[0][0]);

    int arow[4];
    #pragma unroll
    for (int p = 0; p < 4; p++) {
        int sl = rslot[(tid + p*256) >> 3];
        arow[p] = (sl < 0) ? 0 : (sl >> 1);
    }

    float c1[2][4][4], c3[2][4][4];
    #pragma unroll
    for (int i = 0; i < 2; i++)
        #pragma unroll
        for (int j = 0; j < 4; j++)
            #pragma unroll
            for (int r = 0; r < 4; r++) { c1[i][j][r] = 0.f; c3[i][j][r] = 0.f; }

    const int nkt = DMODEL >> 6;

    #define ISSUE_W13(s, k0)                                                       \
    {                                                                              \
        _Pragma("unroll")                                                          \
        for (int p = 0; p < 4; p++) {                                              \
            int lin = tid + p*256;                                                 \
            int row = lin >> 3, ch = lin & 7;                                      \
            uint32_t so = ((s)*8192 + row*64 + ((ch ^ (row & 7)) << 3)) * 2;       \
            CP16(sA + so, g_hn16 + (size_t)arow[p]*DMODEL + (k0) + ch*8);          \
        }                                                                          \
        _Pragma("unroll")                                                          \
        for (int p = 0; p < 2; p++) {                                              \
            int lin = tid + p*256;                                                 \
            int row = lin >> 3, ch = lin & 7;                                      \
            uint32_t so = ((s)*4096 + row*64 + ((ch ^ (row & 7)) << 3)) * 2;       \
            CP16(sB1 + so, B1 + (size_t)(n0+row)*DMODEL + (k0) + ch*8);            \
            CP16(sB3 + so, B3 + (size_t)(n0+row)*DMODEL + (k0) + ch*8);            \
        }                                                                          \
    }

    ISSUE_W13(0, 0);
    CPCOMMIT();

    for (int kt = 0; kt < nkt; kt++) {
        if (kt + 1 < nkt) {
            ISSUE_W13((kt+1) & 1, (kt+1) << 6);
            CPCOMMIT();
            CPWAIT(1);
        } else {
            CPWAIT(0);
        }
        __syncthreads();

        const __half* as  = &As [kt & 1][0];
        const __half* b1s = &B1s[kt & 1][0];
        const __half* b3s = &B3s[kt & 1][0];
        #pragma unroll
        for (int ks = 0; ks < 4; ks++) {
            uint32_t a[2][4], b1[4][2], b3[4][2];
            #pragma unroll
            for (int i = 0; i < 2; i++) {
                int r = wm + i*16 + g;
                a[i][0] = LDH(as, r,     2*ks,   2*tg);
                a[i][1] = LDH(as, r + 8, 2*ks,   2*tg);
                a[i][2] = LDH(as, r,     2*ks+1, 2*tg);
                a[i][3] = LDH(as, r + 8, 2*ks+1, 2*tg);
            }
            #pragma unroll
            for (int j = 0; j < 4; j++) {
                int r = wn + j*8 + g;
                b1[j][0] = LDH(b1s, r, 2*ks,   2*tg);
                b1[j][1] = LDH(b1s, r, 2*ks+1, 2*tg);
                b3[j][0] = LDH(b3s, r, 2*ks,   2*tg);
                b3[j][1] = LDH(b3s, r, 2*ks+1, 2*tg);
            }
            #pragma unroll
            for (int i = 0; i < 2; i++)
                #pragma unroll
                for (int j = 0; j < 4; j++) {
                    mma_f16(c1[i][j], a[i], b1[j]);
                    mma_f16(c3[i][j], a[i], b3[j]);
                }
        }
        __syncthreads();
    }

    #pragma unroll
    for (int i = 0; i < 2; i++) {
        int l0 = wm + i*16 + g;
        int l1 = l0 + 8;
        int s0 = rslot[l0], s1 = rslot[l1];
        #pragma unroll
        for (int j = 0; j < 4; j++) {
            int cb = n0 + wn + j*8 + tg*2;
            if (s0 >= 0) {
                float t1x = c1[i][j][0], t1y = c1[i][j][1];
                float x0 = t1x/(1.f + __expf(-t1x)) * c3[i][j][0];
                float x1 = t1y/(1.f + __expf(-t1y)) * c3[i][j][1];
                *(__half2*)&g_hg16[(size_t)s0*FF + cb] = __floats2half2_rn(x0, x1);
            }
            if (s1 >= 0) {
                float t1x = c1[i][j][2], t1y = c1[i][j][3];
                float x0 = t1x/(1.f + __expf(-t1x)) * c3[i][j][2];
                float x1 = t1y/(1.f + __expf(-t1y)) * c3[i][j][3];
                *(__half2*)&g_hg16[(size_t)s1*FF + cb] = __floats2half2_rn(x0, x1);
            }
        }
    }
}

// ---------------- gathered fp16 NT GEMM for MoE w2 pass (fp32 out) ----------------
__global__ void __launch_bounds__(256, 2) gemm_h_gather(int asel, int bid, size_t strideB,
                                                        int cid, int N, int Kd)
{
    const int e  = blockIdx.z;
    const int ne = g_ecnt[e];
    const int m0 = blockIdx.y * 128;
    if (m0 >= ne) return;
    const int n0 = blockIdx.x * 128;

    const __half* A = (asel == 0) ? g_hn16 : g_hg16;
    const __half* B = resolve_hbuf(bid) + (size_t)e * strideB;
    const int* list = g_elist + e*TOK;

    __shared__ __half As[2][128*64];
    __shared__ __half Bs[2][128*64];
    __shared__ int rslot[128];

    const int tid = threadIdx.x;
    if (tid < 128) {
        int m = m0 + tid;
        rslot[tid] = (m < ne) ? list[m] : -1;
    }
    __syncthreads();

    const int warp = tid >> 5, lane = tid & 31;
    const int wm   = (warp & 3) * 32;
    const int wn   = (warp >> 2) * 64;
    const int g    = lane >> 2, tg = lane & 3;

    const uint32_t sA = (uint32_t)__cvta_generic_to_shared(&As[0][0]);
    const uint32_t sB = (uint32_t)__cvta_generic_to_shared(&Bs[0][0]);

    int arow[4];
    #pragma unroll
    for (int p = 0; p < 4; p++) {
        int lin = tid + p*256;
        int sl  = rslot[lin >> 3];
        arow[p] = (sl < 0) ? 0 : ((asel == 0) ? (sl >> 1) : sl);
    }

    float c[2][8][4];
    #pragma unroll
    for (int i = 0; i < 2; i++)
        #pragma unroll
        for (int j = 0; j < 8; j++)
            #pragma unroll
            for (int r = 0; r < 4; r++) c[i][j][r] = 0.f;

    const int nkt = Kd >> 6;

    #define ISSUE_GATHER(s, k0)                                                    \
    {                                                                              \
        _Pragma("unroll")                                                          \
        for (int p = 0; p < 4; p++) {                                              \
            int lin = tid + p*256;                                                 \
            int row = lin >> 3, ch = lin & 7;                                      \
            uint32_t so = ((s)*8192 + row*64 + ((ch ^ (row & 7)) << 3)) * 2;       \
            CP16(sA + so, A + (size_t)arow[p]*Kd + (k0) + ch*8);                   \
            CP16(sB + so, B + (size_t)(n0+row)*Kd + (k0) + ch*8);                  \
        }                                                                          \
    }

    ISSUE_GATHER(0, 0);
    CPCOMMIT();

    for (int kt = 0; kt < nkt; kt++) {
        if (kt + 1 < nkt) {
            ISSUE_GATHER((kt+1) & 1, (kt+1) << 6);
            CPCOMMIT();
            CPWAIT(1);
        } else {
            CPWAIT(0);
        }
        __syncthreads();

        const __half* as = &As[kt & 1][0];
        const __half* bs = &Bs[kt & 1][0];
        #pragma unroll
        for (int ks = 0; ks < 4; ks++) {
            uint32_t a[2][4], b[8][2];
            #pragma unroll
            for (int i = 0; i < 2; i++) {
                int r = wm + i*16 + g;
                a[i][0] = LDH(as, r,     2*ks,   2*tg);
                a[i][1] = LDH(as, r + 8, 2*ks,   2*tg);
                a[i][2] = LDH(as, r,     2*ks+1, 2*tg);
                a[i][3] = LDH(as, r + 8, 2*ks+1, 2*tg);
            }
            #pragma unroll
            for (int j = 0; j < 8; j++) {
                int r = wn + j*8 + g;
                b[j][0] = LDH(bs, r, 2*ks,   2*tg);
                b[j][1] = LDH(bs, r, 2*ks+1, 2*tg);
            }
            #pragma unroll
            for (int i = 0; i < 2; i++)
                #pragma unroll
                for (int j = 0; j < 8; j++) mma_f16(c[i][j], a[i], b[j]);
        }
        __syncthreads();
    }

    float* C = resolve_buf(cid, nullptr);
    #pragma unroll
    for (int i = 0; i < 2; i++) {
        int l0 = wm + i*16 + g;
        int l1 = l0 + 8;
        int s0 = rslot[l0], s1 = rslot[l1];
        #pragma unroll
        for (int j = 0; j < 8; j++) {
            int cb = n0 + wn + j*8 + tg*2;
            if (s0 >= 0) { float2 v = {c[i][j][0], c[i][j][1]}; *(float2*)&C[(size_t)s0*N + cb] = v; }
            if (s1 >= 0) { float2 v = {c[i][j][2], c[i][j][3]}; *(float2*)&C[(size_t)s1*N + cb] = v; }
        }
    }
}

// ---------------- tensor-core flash attention ----------------
__global__ void __launch_bounds__(128) flash16_kernel(const int* __restrict__ causal_p)
{
    __shared__ __half Qs[64*64];
    __shared__ __half Ks[64*64];
    __shared__ __half Vt[64*72];   // transposed [d][j], padded rows

    const int b  = blockIdx.z;
    const int hh = blockIdx.y;
    const int q0 = blockIdx.x * 64;
    const int t  = threadIdx.x;
    const int warp = t >> 5, lane = t & 31;
    const int g = lane >> 2, tg = lane & 3;

    const uint32_t sQ = (uint32_t)__cvta_generic_to_shared(Qs);
    const uint32_t sK = (uint32_t)__cvta_generic_to_shared(Ks);

    size_t qgbase = ((size_t)(b*SEQ + q0))*DMODEL + hh*HDIM;
    #pragma unroll
    for (int p = 0; p < 4; p++) {
        int lin = t + p*128;
        int row = lin >> 3, ch = lin & 7;
        uint32_t so = (row*64 + ((ch ^ (row & 7)) << 3)) * 2;
        CP16(sQ + so, g_q16 + qgbase + (size_t)row*DMODEL + ch*8);
    }
    CPCOMMIT();

    const int causal = *causal_p;
    const int kend = causal ? (q0 + 64) : SEQ;

    float m0 = -3.4e38f, m1 = -3.4e38f, l0 = 0.f, l1 = 0.f;
    float co[8][4];
    #pragma unroll
    for (int j = 0; j < 8; j++)
        #pragma unroll
        for (int r = 0; r < 4; r++) co[j][r] = 0.f;

    CPWAIT(0);
    __syncthreads();

    for (int k0 = 0; k0 < kend; k0 += 64) {
        size_t kgbase = ((size_t)(b*SEQ + k0))*DMODEL + hh*HDIM;
        #pragma unroll
        for (int p = 0; p < 4; p++) {
            int lin = t + p*128;
            int row = lin >> 3, ch = lin & 7;
            uint32_t so = (row*64 + ((ch ^ (row & 7)) << 3)) * 2;
            CP16(sK + so, g_k16 + kgbase + (size_t)row*DMODEL + ch*8);
        }
        CPCOMMIT();
        #pragma unroll
        for (int p = 0; p < 4; p++) {
            int lin = t + p*128;
            int row = lin >> 3, ch = lin & 7;
            uint4 v = *(const uint4*)(g_v16 + kgbase + (size_t)row*DMODEL + ch*8);
            const __half* hv = (const __half*)&v;
            #pragma unroll
            for (int i = 0; i < 8; i++) Vt[(ch*8 + i)*72 + row] = hv[i];
        }
        CPWAIT(0);
        __syncthreads();

        float s[8][4];
        #pragma unroll
        for (int j = 0; j < 8; j++)
            #pragma unroll
            for (int r = 0; r < 4; r++) s[j][r] = 0.f;

        #pragma unroll
        for (int ks = 0; ks < 4; ks++) {
            uint32_t a[4];
            int r = warp*16 + g;
            a[0] = LDH(Qs, r,     2*ks,   2*tg);
            a[1] = LDH(Qs, r + 8, 2*ks,   2*tg);
            a[2] = LDH(Qs, r,     2*ks+1, 2*tg);
            a[3] = LDH(Qs, r + 8, 2*ks+1, 2*tg);
            #pragma unroll
            for (int j = 0; j < 8; j++) {
                uint32_t bb[2];
                bb[0] = LDH(Ks, 8*j + g, 2*ks,   2*tg);
                bb[1] = LDH(Ks, 8*j + g, 2*ks+1, 2*tg);
                mma_f16(s[j], a, bb);
            }
        }

        const int row0 = q0 + warp*16 + g;
        const int row1 = row0 + 8;
        const bool maskt = causal && (k0 == q0);
        float mx0 = -3.4e38f, mx1 = -3.4e38f;
        #pragma unroll
        for (int j = 0; j < 8; j++) {
            int c0 = k0 + 8*j + 2*tg, c1 = c0 + 1;
            s[j][0] *= 0.125f; s[j][1] *= 0.125f; s[j][2] *= 0.125f; s[j][3] *= 0.125f;
            if (maskt) {
                if (c0 > row0) s[j][0] = -1e30f;
                if (c1 > row0) s[j][1] = -1e30f;
                if (c0 > row1) s[j][2] = -1e30f;
                if (c1 > row1) s[j][3] = -1e30f;
            }
            mx0 = fmaxf(mx0, fmaxf(s[j][0], s[j][1]));
            mx1 = fmaxf(mx1, fmaxf(s[j][2], s[j][3]));
        }
        mx0 = fmaxf(mx0, __shfl_xor_sync(0xffffffffu, mx0, 1));
        mx0 = fmaxf(mx0, __shfl_xor_sync(0xffffffffu, mx0, 2));
        mx1 = fmaxf(mx1, __shfl_xor_sync(0xffffffffu, mx1, 1));
        mx1 = fmaxf(mx1, __shfl_xor_sync(0xffffffffu, mx1, 2));

        float mn0 = fmaxf(m0, mx0), mn1 = fmaxf(m1, mx1);
        float al0 = __expf(m0 - mn0), al1 = __expf(m1 - mn1);
        float sm0 = 0.f, sm1 = 0.f;
        #pragma unroll
        for (int j = 0; j < 8; j++) {
            s[j][0] = __expf(s[j][0] - mn0);
            s[j][1] = __expf(s[j][1] - mn0);
            s[j][2] = __expf(s[j][2] - mn1);
            s[j][3] = __expf(s[j][3] - mn1);
            sm0 += s[j][0] + s[j][1];
            sm1 += s[j][2] + s[j][3];
        }
        sm0 += __shfl_xor_sync(0xffffffffu, sm0, 1);
        sm0 += __shfl_xor_sync(0xffffffffu, sm0, 2);
        sm1 += __shfl_xor_sync(0xffffffffu, sm1, 1);
        sm1 += __shfl_xor_sync(0xffffffffu, sm1, 2);

        l0 = l0*al0 + sm0; l1 = l1*al1 + sm1;
        m0 = mn0; m1 = mn1;

        #pragma unroll
        for (int j = 0; j < 8; j++) {
            co[j][0] *= al0; co[j][1] *= al0;
            co[j][2] *= al1; co[j][3] *= al1;
        }

        #pragma unroll
        for (int ks = 0; ks < 4; ks++) {
            uint32_t a[4];
            a[0] = packh2(s[2*ks  ][0], s[2*ks  ][1]);
            a[1] = packh2(s[2*ks  ][2], s[2*ks  ][3]);
            a[2] = packh2(s[2*ks+1][0], s[2*ks+1][1]);
            a[3] = packh2(s[2*ks+1][2], s[2*ks+1][3]);
            #pragma unroll
            for (int db = 0; db < 8; db++) {
                uint32_t bb[2];
                bb[0] = *(const uint32_t*)&Vt[(8*db + g)*72 + ks*16     + 2*tg];
                bb[1] = *(const uint32_t*)&Vt[(8*db + g)*72 + ks*16 + 8 + 2*tg];
                mma_f16(co[db], a, bb);
            }
        }
        __syncthreads();
    }

    float inv0 = 1.f/l0, inv1 = 1.f/l1;
    size_t ob0 = ((size_t)(b*SEQ + q0 + warp*16 + g))*DMODEL + hh*HDIM;
    size_t ob1 = ob0 + (size_t)8*DMODEL;
    #pragma unroll
    for (int db = 0; db < 8; db++) {
        *(__half2*)&g_ctx16[ob0 + 8*db + 2*tg] = __floats2half2_rn(co[db][0]*inv0, co[db][1]*inv0);
        *(__half2*)&g_ctx16[ob1 + 8*db + 2*tg] = __floats2half2_rn(co[db][2]*inv1, co[db][3]*inv1);
    }
}

// ---------------- router ----------------
__global__ void router_kernel(const float* __restrict__ RW, const float* __restrict__ RB)
{
    int t = blockIdx.x;
    int e = threadIdx.x >> 4;
    int l = threadIdx.x & 15;
    const float* x = g_hn + (size_t)t*DMODEL;
    const float* w = RW + (size_t)e*DMODEL;
    float s = 0.f;
    for (int i = l; i < DMODEL; i += 16) s += x[i]*w[i];
    #pragma unroll
    for (int o = 8; o; o >>= 1) s += __shfl_down_sync(0xffffffffu, s, o, 16);
    __shared__ float lg[NE];
    if (l == 0) lg[e] = s + RB[e];
    __syncthreads();
    if (threadIdx.x == 0) {
        int i0 = 0; float v0 = lg[0];
        #pragma unroll
        for (int i = 1; i < NE; i++) if (lg[i] > v0) { v0 = lg[i]; i0 = i; }
        int i1 = -1; float v1 = -3.4e38f;
        #pragma unroll
        for (int i = 0; i < NE; i++) if (i != i0 && lg[i] > v1) { v1 = lg[i]; i1 = i; }
        float ex = __expf(v1 - v0);
        float p0 = 1.f/(1.f + ex);
        float p1 = ex/(1.f + ex);
        int s0 = t*2, s1 = t*2 + 1;
        int pos0 = atomicAdd(&g_ecnt[i0], 1); g_elist[i0*TOK + pos0] = s0;
        int pos1 = atomicAdd(&g_ecnt[i1], 1); g_elist[i1*TOK + pos1] = s1;
        g_gate[s0] = p0;
        g_gate[s1] = p1;
    }
}

// ---------------- final residual combine ----------------
__global__ void final_kernel(float* __restrict__ out)
{
    int idx = blockIdx.x*256 + threadIdx.x;
    if (idx >= TOK*DMODEL) return;
    int tok = idx >> 10, d = idx & 1023;
    out[idx] = g_h[idx]
             + g_gate[tok*2    ] * g_y2[(size_t)(tok*2    )*DMODEL + d]
             + g_gate[tok*2 + 1] * g_y2[(size_t)(tok*2 + 1)*DMODEL + d];
}

// ---------------- host launcher ----------------
extern "C" void kernel_launch(void* const* d_in, const int* in_sizes, int n_in,
                              void* d_out, int out_size)
{
    const float* q    = (const float*)d_in[0];
    const float* fc   = (const float*)d_in[3];
    const float* fs   = (const float*)d_in[4];
    const float* anw  = (const float*)d_in[5];
    const float* fnw  = (const float*)d_in[6];
    const float* wq   = (const float*)d_in[7];
    const float* wk   = (const float*)d_in[8];
    const float* wv   = (const float*)d_in[9];
    const float* wo   = (const float*)d_in[10];
    const float* rw   = (const float*)d_in[11];
    const float* rb   = (const float*)d_in[12];
    const float* w1   = (const float*)d_in[13];
    const float* w2   = (const float*)d_in[14];
    const float* w3   = (const float*)d_in[15];
    const int*   cz   = (const int*)d_in[16];
    float* out = (float*)d_out;

    // all weight conversions in one launch
    {
        size_t total4 = (size_t)4*DMODEL*DMODEL/4 + (size_t)3*NE*FF*DMODEL/4;
        int blocks = (int)((total4 + 255)/256);
        f2h_all<<<blocks, 256>>>((const float4*)wq, (const float4*)wk, (const float4*)wv,
                                 (const float4*)wo, (const float4*)w1, (const float4*)w3,
                                 (const float4*)w2);
    }

    rmsnorm_kernel<<<TOK, 256>>>(q, BUF_EXT, -1, HB_QN16, anw);

    // fused QKV projections + RoPE epilogue
    gemm_qkv<<<dim3(DMODEL/128, TOK/128, 3), 256>>>(fc, fs);

    flash16_kernel<<<dim3(SEQ/64, NH, 4), 128>>>(cz);

    dim3 gproj(DMODEL/128, TOK/128);
    gemm_h<<<gproj, 256>>>(HB_CTX16, HB_WO, BUF_H, 0, q, 1, DMODEL, DMODEL);

    rmsnorm_kernel<<<TOK, 256>>>(nullptr, BUF_H, BUF_HN, HB_HN16, fnw);

    router_kernel<<<TOK, 128>>>(rw, rb);

    // fused w1||w3 -> hg16 (silu applied in epilogue)
    gemm_w13<<<dim3(FF/64, TOK/128, NE), 256>>>();

    // w2 pass -> y2 (fp32)
    gemm_h_gather<<<dim3(DMODEL/128, TOK/128, NE), 256>>>(1, HB_W2, (size_t)DMODEL*FF, BUF_Y2, DMODEL, FF);

    final_kernel<<<(TOK*DMODEL + 255)/256, 256>>>(out);
}